// round 14
// baseline (speedup 1.0000x reference)
#include <cuda_runtime.h>
#include <cuda_bf16.h>
#include <math.h>

#define NPROP 2000
#define NGT   100
#define TR    200
#define PM    66      // POS_MAX = int(200*0.33)
#define HH    512
#define WW    512
#define MS    28
#define PIX   (MS * MS)           // 784
#define BT    512                 // threads per block
#define PWPB  10                  // proposals (classify warps) per block
#define BPB   200                 // blocks per batch (= TR; each owns one output row)
#define NBLK  (2 * BPB)           // 400

// inter-block state (no allocs allowed -> device globals; overwrite-or-reset only)
__device__ unsigned g_blockbits[2][BPB];  // per classify block: posbits | negbits<<10
__device__ int      g_done[2];            // classify-done counter (reset by 200th waiter)
__device__ int      g_mdone[2];           // wait-passed counter  (reset by 200th waiter)
__device__ unsigned g_maskflags;          // OR-accumulated dtype probe (idempotent)

__device__ __forceinline__ float cvtf(float v)          { return v; }
__device__ __forceinline__ float cvtf(int v)            { return (float)v; }
__device__ __forceinline__ float cvtf(unsigned char v)  { return (float)v; }
__device__ __forceinline__ float cvtf(__nv_bfloat16 v)  { return __bfloat162float(v); }

// r-th (0-based) selected proposal from 200 summary words with inclusive cums.
// pos: low 10 bits, neg: high 10 bits.
__device__ __forceinline__ int sel200(const int* cum, const unsigned* bits, int r, int neg) {
    int lo = 0, hi = BPB - 1;
    while (lo < hi) { int mid = (lo + hi) >> 1; if (cum[mid] > r) hi = mid; else lo = mid + 1; }
    int prev = lo ? cum[lo - 1] : 0;
    unsigned w = neg ? (bits[lo] >> 10) : (bits[lo] & 0x3FFu);
    int rr = r - prev;
    while (rr--) w &= w - 1;
    return lo * PWPB + __ffs(w) - 1;
}

// Warp-collective fg-IoU argmax for one proposal box (cross-mult compare,
// ascending-g strict >, min-index tie-break == jnp.argmax). All lanes return g.
__device__ __forceinline__ int argmax_fg_warp(
    float p0, float p1, float p2, float p3,
    const float4* gt4, const unsigned char* fg, int lane)
{
    const float a1 = (p2 - p0) * (p3 - p1);
    float bestI = -1.0f, bestU = 1.0f;
    int bi = 0;
    #pragma unroll
    for (int t = 0; t < 4; t++) {
        int g = lane + t * 32;
        if (g < NGT && fg[g]) {
            float4 q = gt4[g];
            float y1 = fmaxf(p0, q.x);
            float x1 = fmaxf(p1, q.y);
            float y2 = fminf(p2, q.z);
            float x2 = fminf(p3, q.w);
            float inter = fmaxf(x2 - x1, 0.0f) * fmaxf(y2 - y1, 0.0f);
            float a2 = (q.z - q.x) * (q.w - q.y);
            float un = a1 + a2 - inter;
            if (inter * bestU > bestI * un) { bestI = inter; bestU = un; bi = g; }
        }
    }
    #pragma unroll
    for (int off = 16; off; off >>= 1) {
        float oI = __shfl_xor_sync(0xffffffffu, bestI, off);
        float oU = __shfl_xor_sync(0xffffffffu, bestU, off);
        int   og = __shfl_xor_sync(0xffffffffu, bi,    off);
        float l = oI * bestU, r = bestI * oU;
        if (l > r || (l == r && og < bi)) { bestI = oI; bestU = oU; bi = og; }
    }
    return bi;
}

// ---------------------------------------------------------------------------
// 400 blocks x 512 (single wave). R13 structure, classify loop thinned:
// float4 GT loads, branch-free threshold test via (thP, thC) float2
// (INF = never passes), invalid-proposal early-out.
// ---------------------------------------------------------------------------
__global__ __launch_bounds__(BT, 3) void dtl_fused(
    const float* __restrict__ props,
    const int*   __restrict__ cls,
    const float* __restrict__ gtb,
    const void*  __restrict__ masks,
    float*       __restrict__ out)
{
    const int tid = threadIdx.x;
    const int b   = blockIdx.x / BPB;        // batch
    const int k   = blockIdx.x % BPB;        // block-in-batch == output row
    const int wid  = tid >> 5;
    const int lane = tid & 31;

    __shared__ float4        s_gt4[NGT];
    __shared__ float2        s_th[NGT];      // (thP, thC): 0.5/0.001 or +INF
    __shared__ int           s_cls[NGT];
    __shared__ unsigned char s_fg[NGT];
    __shared__ unsigned char s_p10[PWPB], s_n10[PWPB];
    __shared__ unsigned      s_bits[224];
    __shared__ int           s_cumP[224], s_cumN[224];
    __shared__ int           s_wtP[8], s_wtN[8];
    __shared__ int           s_Np, s_Nn;
    __shared__ int           s_rowg[2];
    __shared__ float         s_rbox[2][4];
    __shared__ int           s_go;

    const float* P = props + (size_t)b * NPROP * 4;
    const float* G = gtb   + (size_t)b * NGT * 4;
    const int*   C = cls   + (size_t)b * NGT;

    // EARLY: issue this warp's proposal load immediately (overlaps shared setup)
    float4 pv = make_float4(0.f, 0.f, 0.f, 0.f);
    if (wid < PWPB) pv = __ldg(&((const float4*)P)[k * PWPB + wid]);

    if (tid < NGT) {
        float4 gv = ((const float4*)G)[tid];
        s_gt4[tid] = gv;
        bool vg = (fabsf(gv.x)+fabsf(gv.y)+fabsf(gv.z)+fabsf(gv.w)) > 0.0f;
        int c = C[tid];
        s_cls[tid] = c;
        bool fg = (vg && c > 0);
        bool cr = (vg && c < 0);
        s_fg[tid] = fg ? 1 : 0;
        const float INF = __int_as_float(0x7F800000);
        s_th[tid] = make_float2(fg ? 0.5f : INF, cr ? 0.001f : INF);
    }

    // dtype probe on classify-idle warps 10..13 of block 0 (zero skew)
    if (blockIdx.x == 0 && wid >= 10 && wid < 14) {
        const unsigned* maskw = (const unsigned*)masks;
        int t0 = (wid - 10) * 32 + lane;       // 0..127
        unsigned local = 0u;
        #pragma unroll
        for (int it = 0; it < 16; it++) {
            unsigned v = maskw[t0 + it * 128];
            if (v == 0u || v == 1u) continue;                        // i32-compatible
            else if (v == 0x3F803F80u || v == 0x00003F80u) local |= 4u;  // bf16 pair
            else if (v == 0x3F800000u)                     local |= 2u;  // f32 1.0
            else if ((v & ~0x01010101u) == 0u)             local |= 1u;  // u8 bytes
        }
        local = __reduce_or_sync(0xffffffffu, local);
        if (lane == 0 && local) atomicOr(&g_maskflags, local);
    }
    __syncthreads();

    // ---- classify (anyP/anyC only, branch-free thresholds): warps 0..9 ----
    if (wid < PWPB) {
        const float p0 = pv.x, p1 = pv.y, p2 = pv.z, p3 = pv.w;
        const bool vp = (fabsf(p0)+fabsf(p1)+fabsf(p2)+fabsf(p3)) > 0.0f;
        bool anyP = false, anyC = false;
        if (vp) {                                  // invalid proposal: both false
            const float a1 = (p2 - p0) * (p3 - p1);
            #pragma unroll
            for (int t = 0; t < 4; t++) {
                int g = lane + t * 32;
                if (g < NGT) {
                    float4 q  = s_gt4[g];
                    float2 th = s_th[g];
                    float y1 = fmaxf(p0, q.x);
                    float x1 = fmaxf(p1, q.y);
                    float y2 = fminf(p2, q.z);
                    float x2 = fminf(p3, q.w);
                    float inter = fmaxf(x2 - x1, 0.0f) * fmaxf(y2 - y1, 0.0f);
                    float a2 = (q.z - q.x) * (q.w - q.y);
                    float un = a1 + a2 - inter;
                    anyP |= (inter >= th.x * un);  // fg:    iou >= 0.5
                    anyC |= (inter >= th.y * un);  // crowd: iou >= 0.001
                }
            }
        }
        anyP = __ballot_sync(0xffffffffu, anyP) != 0u;
        anyC = __ballot_sync(0xffffffffu, anyC) != 0u;
        if (lane == 0) {
            s_p10[wid] = (unsigned char)((anyP && vp) ? 1 : 0);
            s_n10[wid] = (unsigned char)((!anyP && !anyC && vp) ? 1 : 0);
        }
    }
    __syncthreads();

    // ---- barrier: cg-style release (tid0-only fence), per-batch 200 arrivals ----
    if (tid == 0) {
        unsigned w = 0u;
        #pragma unroll
        for (int i = 0; i < PWPB; i++)
            w |= ((unsigned)s_p10[i] << i) | ((unsigned)s_n10[i] << (10 + i));
        g_blockbits[b][k] = w;
        __threadfence();                       // release blockbits
        atomicAdd(&g_done[b], 1);
        while (*((volatile int*)&g_done[b]) < BPB) __nanosleep(32);
        __threadfence();                       // acquire
        s_go = 1;
    }
    __syncthreads();
    (void)s_go;
    // overlapped reset (200th passer resets)
    if (tid == 0) {
        int c = atomicAdd(&g_mdone[b], 1);
        if (c == BPB - 1) { g_done[b] = 0; g_mdone[b] = 0; __threadfence(); }
    }

    // ---- light self-finalize: scan 200 summary words ----
    unsigned wbits = 0u; int pcnt = 0, ncnt = 0;
    if (tid < BPB) {
        wbits = g_blockbits[b][tid];
        pcnt = __popc(wbits & 0x3FFu);
        ncnt = __popc(wbits >> 10);
    }
    if (tid < 224) s_bits[tid] = wbits;
    int ip = pcnt, in_ = ncnt;
    if (wid < 7) {
        #pragma unroll
        for (int off = 1; off < 32; off <<= 1) {
            int a = __shfl_up_sync(0xffffffffu, ip,  off);
            int c = __shfl_up_sync(0xffffffffu, in_, off);
            if (lane >= off) { ip += a; in_ += c; }
        }
        if (lane == 31) { s_wtP[wid] = ip; s_wtN[wid] = in_; }
    }
    __syncthreads();
    if (tid == 0) {
        int rp = 0, rn = 0;
        #pragma unroll
        for (int i = 0; i < 7; i++) {
            int a = s_wtP[i], c = s_wtN[i];
            s_wtP[i] = rp; s_wtN[i] = rn;
            rp += a; rn += c;
        }
        int Np = min(rp, PM);
        const float R = (float)(1.0 / 0.33);
        int want = (int)floorf(R * (float)Np) - Np;
        int Nn = min(want, rn);
        Nn = max(Nn, 0);
        s_Np = Np;
        s_Nn = min(Nn, TR - Np);
    }
    __syncthreads();
    if (tid < BPB && wid < 7) {
        s_cumP[tid] = ip  + s_wtP[wid];        // inclusive
        s_cumN[tid] = in_ + s_wtN[wid];
    }
    __syncthreads();

    const int Np = s_Np, Nn = s_Nn;
    const int T    = Np * PIX;                 // total live pixels this batch
    const int base = (int)(((long long)k * T) / BPB);
    const int endp = (int)(((long long)(k + 1) * T) / BPB);
    const int len  = endp - base;              // <= 259 < BT
    const int r0   = (len > 0) ? (base / PIX) : 0;

    // chunk-row setup with lazy argmax: warp 0 -> slot 0 (row r0),
    // warp 1 -> slot 1 (row (endp-1)/PIX if distinct)
    if (wid < 2 && len > 0) {
        const int rr = (wid == 0) ? r0 : (endp - 1) / PIX;
        if (wid == 0 || rr != r0) {
            int n;
            if (lane == 0) n = sel200(s_cumP, s_bits, rr, 0);
            n = __shfl_sync(0xffffffffu, n, 0);
            float4 bv = __ldg(&((const float4*)P)[n]);
            int g = argmax_fg_warp(bv.x, bv.y, bv.z, bv.w, s_gt4, s_fg, lane);
            if (lane == 0) {
                s_rbox[wid][0] = bv.x; s_rbox[wid][1] = bv.y;
                s_rbox[wid][2] = bv.z; s_rbox[wid][3] = bv.w;
                s_rowg[wid] = g;
            }
        }
    }

    // row-k scalar outputs with lazy argmax: warp 9 (tids 288..319 — never
    // gather threads since len <= 259; overlaps gathers after the sync)
    if (wid == 9) {
        float* ro = out + (size_t)(b * TR + k) * 4;
        float* cl = out + 1600 + (size_t)(b * TR + k);
        float* de = out + 2000 + (size_t)(b * TR + k) * 4;
        if (k < Np) {
            int n;
            if (lane == 0) n = sel200(s_cumP, s_bits, k, 0);
            n = __shfl_sync(0xffffffffu, n, 0);
            float4 bv = __ldg(&((const float4*)P)[n]);
            int g = argmax_fg_warp(bv.x, bv.y, bv.z, bv.w, s_gt4, s_fg, lane);
            if (lane == 0) {
                float p0 = bv.x, p1 = bv.y, p2 = bv.z, p3 = bv.w;
                ro[0] = p0; ro[1] = p1; ro[2] = p2; ro[3] = p3;
                cl[0] = (float)s_cls[g];
                float h  = p2 - p0, w2 = p3 - p1;
                float cy = p0 + 0.5f * h, cx = p1 + 0.5f * w2;
                float4 gq = s_gt4[g];
                float gh = gq.z - gq.x, gw = gq.w - gq.y;
                float gcy = gq.x + 0.5f * gh, gcx = gq.y + 0.5f * gw;
                de[0] = ((gcy - cy) / h)  / 0.1f;
                de[1] = ((gcx - cx) / w2) / 0.1f;
                de[2] = logf(gh / h)  / 0.2f;
                de[3] = logf(gw / w2) / 0.2f;
            }
        } else if (lane == 0) {
            if (k < Np + Nn) {
                int n = sel200(s_cumN, s_bits, k - Np, 1);
                float4 bv = __ldg(&((const float4*)P)[n]);
                ro[0] = bv.x; ro[1] = bv.y; ro[2] = bv.z; ro[3] = bv.w;
                cl[0] = 0.0f;
                de[0] = de[1] = de[2] = de[3] = 0.0f;
            } else {
                ro[0] = ro[1] = ro[2] = ro[3] = 0.0f;
                cl[0] = 0.0f;
                de[0] = de[1] = de[2] = de[3] = 0.0f;
            }
        }
    }
    __syncthreads();

    // ---- gather: one pixel per thread over this block's chunk ----
    if (tid < len) {
        const int p  = base + tid;
        const int j  = p / PIX;
        const int pp = p - j * PIX;
        const int slot = (j != r0) ? 1 : 0;
        const float y1 = s_rbox[slot][0], x1 = s_rbox[slot][1];
        const float y2 = s_rbox[slot][2], x2 = s_rbox[slot][3];
        const int   g  = s_rowg[slot];
        const float sy = ((y2 - y1) * 511.0f) / 27.0f;
        const float sx = ((x2 - x1) * 511.0f) / 27.0f;
        const int i  = pp / MS, kx = pp - i * MS;
        const float ys = y1 * 511.0f + (float)i  * sy;
        const float xs = x1 * 511.0f + (float)kx * sx;
        const float y0f = floorf(ys), x0f = floorf(xs);
        const float wy = ys - y0f, wx = xs - x0f;
        const int y0i = (int)fminf(fmaxf(y0f,        0.0f), 511.0f);
        const int y1i = (int)fminf(fmaxf(y0f + 1.0f, 0.0f), 511.0f);
        const int x0i = (int)fminf(fmaxf(x0f,        0.0f), 511.0f);
        const int x1i = (int)fminf(fmaxf(x0f + 1.0f, 0.0f), 511.0f);
        const unsigned mb = (unsigned)b * (HH * WW * NGT);
        const unsigned i00 = mb + (unsigned)(y0i * WW + x0i) * NGT + g;
        const unsigned i01 = mb + (unsigned)(y0i * WW + x1i) * NGT + g;
        const unsigned i10 = mb + (unsigned)(y1i * WW + x0i) * NGT + g;
        const unsigned i11 = mb + (unsigned)(y1i * WW + x1i) * NGT + g;
        const unsigned mode = g_maskflags;
        float v00, v01, v10, v11;
        if (mode & 4u) {
            const __nv_bfloat16* m = (const __nv_bfloat16*)masks;
            v00 = cvtf(__ldg(m + i00)); v01 = cvtf(__ldg(m + i01));
            v10 = cvtf(__ldg(m + i10)); v11 = cvtf(__ldg(m + i11));
        } else if (mode & 2u) {
            const float* m = (const float*)masks;
            v00 = __ldg(m + i00); v01 = __ldg(m + i01);
            v10 = __ldg(m + i10); v11 = __ldg(m + i11);
        } else if (mode & 1u) {
            const unsigned char* m = (const unsigned char*)masks;
            v00 = cvtf(__ldg(m + i00)); v01 = cvtf(__ldg(m + i01));
            v10 = cvtf(__ldg(m + i10)); v11 = cvtf(__ldg(m + i11));
        } else {
            const int* m = (const int*)masks;
            v00 = cvtf(__ldg(m + i00)); v01 = cvtf(__ldg(m + i01));
            v10 = cvtf(__ldg(m + i10)); v11 = cvtf(__ldg(m + i11));
        }
        float val = (v00 * (1.0f - wx) + v01 * wx) * (1.0f - wy)
                  + (v10 * (1.0f - wx) + v11 * wx) * wy;
        const bool ok = (ys >= 0.0f) && (ys <= 511.0f) && (xs >= 0.0f) && (xs <= 511.0f);
        out[3600 + (size_t)(b * TR + j) * PIX + pp] = ok ? rintf(val) : 0.0f;  // half-even
    }

    // ---- dead-row zeroing (tids >=320, overlaps gathers) ----
    if (tid >= 320 && k >= Np) {
        float* om = out + 3600 + (size_t)(b * TR + k) * PIX;
        for (int p = tid - 320; p < PIX; p += BT - 320) om[p] = 0.0f;
    }
}

// ---------------------------------------------------------------------------
extern "C" void kernel_launch(void* const* d_in, const int* in_sizes, int n_in,
                              void* d_out, int out_size)
{
    const float* props = (const float*)d_in[0];
    const int*   cls   = (const int*)  d_in[1];
    const float* gtb   = (const float*)d_in[2];
    const void*  masks = d_in[3];
    float* out = (float*)d_out;

    dtl_fused<<<NBLK, BT>>>(props, cls, gtb, masks, out);
}

// round 15
// speedup vs baseline: 1.1142x; 1.1142x over previous
#include <cuda_runtime.h>
#include <cuda_bf16.h>
#include <math.h>

#define NPROP 2000
#define NGT   100
#define TR    200
#define PM    66      // POS_MAX = int(200*0.33)
#define HH    512
#define WW    512
#define MS    28
#define PIX   (MS * MS)           // 784
#define BT    512                 // threads per block
#define PWPB  10                  // proposals (classify warps) per block
#define BPB   200                 // blocks per batch (= TR; each owns one output row)
#define NBLK  (2 * BPB)           // 400

// inter-block state (no allocs allowed -> device globals; overwrite-or-reset only)
__device__ unsigned g_blockbits[2][BPB];  // per classify block: posbits | negbits<<10
__device__ int      g_done[2];            // classify-done counter (reset by 200th waiter)
__device__ int      g_mdone[2];           // wait-passed counter  (reset by 200th waiter)
__device__ unsigned g_maskflags;          // OR-accumulated dtype probe (idempotent)

__device__ __forceinline__ float cvtf(float v)          { return v; }
__device__ __forceinline__ float cvtf(int v)            { return (float)v; }
__device__ __forceinline__ float cvtf(unsigned char v)  { return (float)v; }
__device__ __forceinline__ float cvtf(__nv_bfloat16 v)  { return __bfloat162float(v); }

// r-th (0-based) selected proposal from 200 summary words with inclusive cums.
// pos: low 10 bits, neg: high 10 bits.
__device__ __forceinline__ int sel200(const int* cum, const unsigned* bits, int r, int neg) {
    int lo = 0, hi = BPB - 1;
    while (lo < hi) { int mid = (lo + hi) >> 1; if (cum[mid] > r) hi = mid; else lo = mid + 1; }
    int prev = lo ? cum[lo - 1] : 0;
    unsigned w = neg ? (bits[lo] >> 10) : (bits[lo] & 0x3FFu);
    int rr = r - prev;
    while (rr--) w &= w - 1;
    return lo * PWPB + __ffs(w) - 1;
}

// Warp-collective fg-IoU argmax for one proposal box (cross-mult compare,
// ascending-g strict >, min-index tie-break == jnp.argmax). All lanes return g.
__device__ __forceinline__ int argmax_fg_warp(
    float p0, float p1, float p2, float p3,
    const float (*gt)[5], const unsigned char* fg, int lane)
{
    const float a1 = (p2 - p0) * (p3 - p1);
    float bestI = -1.0f, bestU = 1.0f;
    int bi = 0;
    #pragma unroll
    for (int t = 0; t < 4; t++) {
        int g = lane + t * 32;
        if (g < NGT && fg[g]) {
            float q0 = gt[g][0], q1 = gt[g][1], q2 = gt[g][2], q3 = gt[g][3];
            float y1 = fmaxf(p0, q0);
            float x1 = fmaxf(p1, q1);
            float y2 = fminf(p2, q2);
            float x2 = fminf(p3, q3);
            float inter = fmaxf(x2 - x1, 0.0f) * fmaxf(y2 - y1, 0.0f);
            float a2 = (q2 - q0) * (q3 - q1);
            float un = a1 + a2 - inter;
            if (inter * bestU > bestI * un) { bestI = inter; bestU = un; bi = g; }
        }
    }
    #pragma unroll
    for (int off = 16; off; off >>= 1) {
        float oI = __shfl_xor_sync(0xffffffffu, bestI, off);
        float oU = __shfl_xor_sync(0xffffffffu, bestU, off);
        int   og = __shfl_xor_sync(0xffffffffu, bi,    off);
        float l = oI * bestU, r = bestI * oU;
        if (l > r || (l == r && og < bi)) { bestI = oI; bestU = oU; bi = og; }
    }
    return bi;
}

// ---------------------------------------------------------------------------
// 400 blocks x 512 (single wave). R12 structure + LAZY ARGMAX:
// classify computes only anyP/anyC (no per-GT argmax, no g_info array);
// the fg-argmax is recomputed post-barrier only for the <=3 rows each block
// actually touches (warps 0/1: chunk rows; warp 9: row-k scalars).
// ---------------------------------------------------------------------------
__global__ __launch_bounds__(BT, 3) void dtl_fused(
    const float* __restrict__ props,
    const int*   __restrict__ cls,
    const float* __restrict__ gtb,
    const void*  __restrict__ masks,
    float*       __restrict__ out)
{
    const int tid = threadIdx.x;
    const int b   = blockIdx.x / BPB;        // batch
    const int k   = blockIdx.x % BPB;        // block-in-batch == output row
    const int wid  = tid >> 5;
    const int lane = tid & 31;

    __shared__ float         s_gt[NGT][5];   // pad 5: conflict-free strided reads
    __shared__ int           s_cls[NGT];
    __shared__ unsigned char s_fg[NGT], s_crowd[NGT];
    __shared__ unsigned char s_p10[PWPB], s_n10[PWPB];
    __shared__ unsigned      s_bits[224];
    __shared__ int           s_cumP[224], s_cumN[224];
    __shared__ int           s_wtP[8], s_wtN[8];
    __shared__ int           s_Np, s_Nn;
    __shared__ int           s_rowg[2];
    __shared__ float         s_rbox[2][4];
    __shared__ int           s_go;

    const float* P = props + (size_t)b * NPROP * 4;
    const float* G = gtb   + (size_t)b * NGT * 4;
    const int*   C = cls   + (size_t)b * NGT;

    // EARLY: issue this warp's proposal load immediately (overlaps shared setup)
    float4 pv = make_float4(0.f, 0.f, 0.f, 0.f);
    if (wid < PWPB) pv = __ldg(&((const float4*)P)[k * PWPB + wid]);

    if (tid < NGT) {
        float4 gv = ((const float4*)G)[tid];
        s_gt[tid][0] = gv.x; s_gt[tid][1] = gv.y; s_gt[tid][2] = gv.z; s_gt[tid][3] = gv.w;
        bool vg = (fabsf(gv.x)+fabsf(gv.y)+fabsf(gv.z)+fabsf(gv.w)) > 0.0f;
        int c = C[tid];
        s_cls[tid]   = c;
        s_fg[tid]    = (vg && c > 0) ? 1 : 0;
        s_crowd[tid] = (vg && c < 0) ? 1 : 0;
    }

    // dtype probe on classify-idle warps 10..13 of block 0 (zero skew)
    if (blockIdx.x == 0 && wid >= 10 && wid < 14) {
        const unsigned* maskw = (const unsigned*)masks;
        int t0 = (wid - 10) * 32 + lane;       // 0..127
        unsigned local = 0u;
        #pragma unroll
        for (int it = 0; it < 16; it++) {
            unsigned v = maskw[t0 + it * 128];
            if (v == 0u || v == 1u) continue;                        // i32-compatible
            else if (v == 0x3F803F80u || v == 0x00003F80u) local |= 4u;  // bf16 pair
            else if (v == 0x3F800000u)                     local |= 2u;  // f32 1.0
            else if ((v & ~0x01010101u) == 0u)             local |= 1u;  // u8 bytes
        }
        local = __reduce_or_sync(0xffffffffu, local);
        if (lane == 0 && local) atomicOr(&g_maskflags, local);
    }
    __syncthreads();

    // ---- classify (anyP/anyC only — no argmax): warps 0..9 ----
    if (wid < PWPB) {
        const float p0 = pv.x, p1 = pv.y, p2 = pv.z, p3 = pv.w;
        const bool vp = (fabsf(p0)+fabsf(p1)+fabsf(p2)+fabsf(p3)) > 0.0f;
        const float a1 = (p2 - p0) * (p3 - p1);
        bool anyP = false, anyC = false;
        #pragma unroll
        for (int t = 0; t < 4; t++) {
            int g = lane + t * 32;
            if (g < NGT) {
                float q0 = s_gt[g][0], q1 = s_gt[g][1], q2 = s_gt[g][2], q3 = s_gt[g][3];
                float y1 = fmaxf(p0, q0);
                float x1 = fmaxf(p1, q1);
                float y2 = fminf(p2, q2);
                float x2 = fminf(p3, q3);
                float inter = fmaxf(x2 - x1, 0.0f) * fmaxf(y2 - y1, 0.0f);
                float a2 = (q2 - q0) * (q3 - q1);
                float un = a1 + a2 - inter;
                if (s_fg[g]    && (inter >= 0.5f   * un)) anyP = true;  // iou >= 0.5
                if (s_crowd[g] && (inter >= 0.001f * un)) anyC = true;  // iou >= 0.001
            }
        }
        anyP = __ballot_sync(0xffffffffu, anyP) != 0u;
        anyC = __ballot_sync(0xffffffffu, anyC) != 0u;
        if (lane == 0) {
            s_p10[wid] = (unsigned char)((anyP && vp) ? 1 : 0);
            s_n10[wid] = (unsigned char)((!anyP && !anyC && vp) ? 1 : 0);
        }
    }
    __syncthreads();

    // ---- barrier: cg-style release (tid0-only fence), per-batch 200 arrivals ----
    if (tid == 0) {
        unsigned w = 0u;
        #pragma unroll
        for (int i = 0; i < PWPB; i++)
            w |= ((unsigned)s_p10[i] << i) | ((unsigned)s_n10[i] << (10 + i));
        g_blockbits[b][k] = w;
        __threadfence();                       // release blockbits
        atomicAdd(&g_done[b], 1);
        while (*((volatile int*)&g_done[b]) < BPB) __nanosleep(64);
        __threadfence();                       // acquire
        s_go = 1;
    }
    __syncthreads();
    (void)s_go;
    // overlapped reset (200th passer resets)
    if (tid == 0) {
        int c = atomicAdd(&g_mdone[b], 1);
        if (c == BPB - 1) { g_done[b] = 0; g_mdone[b] = 0; __threadfence(); }
    }

    // ---- light self-finalize: scan 200 summary words ----
    unsigned wbits = 0u; int pcnt = 0, ncnt = 0;
    if (tid < BPB) {
        wbits = g_blockbits[b][tid];
        pcnt = __popc(wbits & 0x3FFu);
        ncnt = __popc(wbits >> 10);
    }
    if (tid < 224) s_bits[tid] = wbits;
    int ip = pcnt, in_ = ncnt;
    if (wid < 7) {
        #pragma unroll
        for (int off = 1; off < 32; off <<= 1) {
            int a = __shfl_up_sync(0xffffffffu, ip,  off);
            int c = __shfl_up_sync(0xffffffffu, in_, off);
            if (lane >= off) { ip += a; in_ += c; }
        }
        if (lane == 31) { s_wtP[wid] = ip; s_wtN[wid] = in_; }
    }
    __syncthreads();
    if (tid == 0) {
        int rp = 0, rn = 0;
        #pragma unroll
        for (int i = 0; i < 7; i++) {
            int a = s_wtP[i], c = s_wtN[i];
            s_wtP[i] = rp; s_wtN[i] = rn;
            rp += a; rn += c;
        }
        int Np = min(rp, PM);
        const float R = (float)(1.0 / 0.33);
        int want = (int)floorf(R * (float)Np) - Np;
        int Nn = min(want, rn);
        Nn = max(Nn, 0);
        s_Np = Np;
        s_Nn = min(Nn, TR - Np);
    }
    __syncthreads();
    if (tid < BPB && wid < 7) {
        s_cumP[tid] = ip  + s_wtP[wid];        // inclusive
        s_cumN[tid] = in_ + s_wtN[wid];
    }
    __syncthreads();

    const int Np = s_Np, Nn = s_Nn;
    const int T    = Np * PIX;                 // total live pixels this batch
    const int base = (int)(((long long)k * T) / BPB);
    const int endp = (int)(((long long)(k + 1) * T) / BPB);
    const int len  = endp - base;              // <= 259 < BT
    const int r0   = (len > 0) ? (base / PIX) : 0;

    // chunk-row setup with lazy argmax: warp 0 -> slot 0 (row r0),
    // warp 1 -> slot 1 (row (endp-1)/PIX if distinct)
    if (wid < 2 && len > 0) {
        const int rr = (wid == 0) ? r0 : (endp - 1) / PIX;
        if (wid == 0 || rr != r0) {
            int n;
            if (lane == 0) n = sel200(s_cumP, s_bits, rr, 0);
            n = __shfl_sync(0xffffffffu, n, 0);
            float4 bv = __ldg(&((const float4*)P)[n]);
            int g = argmax_fg_warp(bv.x, bv.y, bv.z, bv.w, s_gt, s_fg, lane);
            if (lane == 0) {
                s_rbox[wid][0] = bv.x; s_rbox[wid][1] = bv.y;
                s_rbox[wid][2] = bv.z; s_rbox[wid][3] = bv.w;
                s_rowg[wid] = g;
            }
        }
    }

    // row-k scalar outputs with lazy argmax: warp 9 (tids 288..319 — never
    // gather threads since len <= 259; overlaps gathers after the sync)
    if (wid == 9) {
        float* ro = out + (size_t)(b * TR + k) * 4;
        float* cl = out + 1600 + (size_t)(b * TR + k);
        float* de = out + 2000 + (size_t)(b * TR + k) * 4;
        if (k < Np) {
            int n;
            if (lane == 0) n = sel200(s_cumP, s_bits, k, 0);
            n = __shfl_sync(0xffffffffu, n, 0);
            float4 bv = __ldg(&((const float4*)P)[n]);
            int g = argmax_fg_warp(bv.x, bv.y, bv.z, bv.w, s_gt, s_fg, lane);
            if (lane == 0) {
                float p0 = bv.x, p1 = bv.y, p2 = bv.z, p3 = bv.w;
                ro[0] = p0; ro[1] = p1; ro[2] = p2; ro[3] = p3;
                cl[0] = (float)s_cls[g];
                float h  = p2 - p0, w2 = p3 - p1;
                float cy = p0 + 0.5f * h, cx = p1 + 0.5f * w2;
                float g0 = s_gt[g][0], g1 = s_gt[g][1], g2 = s_gt[g][2], g3 = s_gt[g][3];
                float gh = g2 - g0, gw = g3 - g1;
                float gcy = g0 + 0.5f * gh, gcx = g1 + 0.5f * gw;
                de[0] = ((gcy - cy) / h)  / 0.1f;
                de[1] = ((gcx - cx) / w2) / 0.1f;
                de[2] = logf(gh / h)  / 0.2f;
                de[3] = logf(gw / w2) / 0.2f;
            }
        } else if (lane == 0) {
            if (k < Np + Nn) {
                int n = sel200(s_cumN, s_bits, k - Np, 1);
                float4 bv = __ldg(&((const float4*)P)[n]);
                ro[0] = bv.x; ro[1] = bv.y; ro[2] = bv.z; ro[3] = bv.w;
                cl[0] = 0.0f;
                de[0] = de[1] = de[2] = de[3] = 0.0f;
            } else {
                ro[0] = ro[1] = ro[2] = ro[3] = 0.0f;
                cl[0] = 0.0f;
                de[0] = de[1] = de[2] = de[3] = 0.0f;
            }
        }
    }
    __syncthreads();

    // ---- gather: one pixel per thread over this block's chunk ----
    if (tid < len) {
        const int p  = base + tid;
        const int j  = p / PIX;
        const int pp = p - j * PIX;
        const int slot = (j != r0) ? 1 : 0;
        const float y1 = s_rbox[slot][0], x1 = s_rbox[slot][1];
        const float y2 = s_rbox[slot][2], x2 = s_rbox[slot][3];
        const int   g  = s_rowg[slot];
        const float sy = ((y2 - y1) * 511.0f) / 27.0f;
        const float sx = ((x2 - x1) * 511.0f) / 27.0f;
        const int i  = pp / MS, kx = pp - i * MS;
        const float ys = y1 * 511.0f + (float)i  * sy;
        const float xs = x1 * 511.0f + (float)kx * sx;
        const float y0f = floorf(ys), x0f = floorf(xs);
        const float wy = ys - y0f, wx = xs - x0f;
        const int y0i = (int)fminf(fmaxf(y0f,        0.0f), 511.0f);
        const int y1i = (int)fminf(fmaxf(y0f + 1.0f, 0.0f), 511.0f);
        const int x0i = (int)fminf(fmaxf(x0f,        0.0f), 511.0f);
        const int x1i = (int)fminf(fmaxf(x0f + 1.0f, 0.0f), 511.0f);
        const unsigned mb = (unsigned)b * (HH * WW * NGT);
        const unsigned i00 = mb + (unsigned)(y0i * WW + x0i) * NGT + g;
        const unsigned i01 = mb + (unsigned)(y0i * WW + x1i) * NGT + g;
        const unsigned i10 = mb + (unsigned)(y1i * WW + x0i) * NGT + g;
        const unsigned i11 = mb + (unsigned)(y1i * WW + x1i) * NGT + g;
        const unsigned mode = g_maskflags;
        float v00, v01, v10, v11;
        if (mode & 4u) {
            const __nv_bfloat16* m = (const __nv_bfloat16*)masks;
            v00 = cvtf(__ldg(m + i00)); v01 = cvtf(__ldg(m + i01));
            v10 = cvtf(__ldg(m + i10)); v11 = cvtf(__ldg(m + i11));
        } else if (mode & 2u) {
            const float* m = (const float*)masks;
            v00 = __ldg(m + i00); v01 = __ldg(m + i01);
            v10 = __ldg(m + i10); v11 = __ldg(m + i11);
        } else if (mode & 1u) {
            const unsigned char* m = (const unsigned char*)masks;
            v00 = cvtf(__ldg(m + i00)); v01 = cvtf(__ldg(m + i01));
            v10 = cvtf(__ldg(m + i10)); v11 = cvtf(__ldg(m + i11));
        } else {
            const int* m = (const int*)masks;
            v00 = cvtf(__ldg(m + i00)); v01 = cvtf(__ldg(m + i01));
            v10 = cvtf(__ldg(m + i10)); v11 = cvtf(__ldg(m + i11));
        }
        float val = (v00 * (1.0f - wx) + v01 * wx) * (1.0f - wy)
                  + (v10 * (1.0f - wx) + v11 * wx) * wy;
        const bool ok = (ys >= 0.0f) && (ys <= 511.0f) && (xs >= 0.0f) && (xs <= 511.0f);
        out[3600 + (size_t)(b * TR + j) * PIX + pp] = ok ? rintf(val) : 0.0f;  // half-even
    }

    // ---- dead-row zeroing (tids >=320, overlaps gathers) ----
    if (tid >= 320 && k >= Np) {
        float* om = out + 3600 + (size_t)(b * TR + k) * PIX;
        for (int p = tid - 320; p < PIX; p += BT - 320) om[p] = 0.0f;
    }
}

// ---------------------------------------------------------------------------
extern "C" void kernel_launch(void* const* d_in, const int* in_sizes, int n_in,
                              void* d_out, int out_size)
{
    const float* props = (const float*)d_in[0];
    const int*   cls   = (const int*)  d_in[1];
    const float* gtb   = (const float*)d_in[2];
    const void*  masks = d_in[3];
    float* out = (float*)d_out;

    dtl_fused<<<NBLK, BT>>>(props, cls, gtb, masks, out);
}